// round 1
// baseline (speedup 1.0000x reference)
#include <cuda_runtime.h>
#include <cuda_bf16.h>

// Problem shapes (fixed by the dataset instance)
#define BB 8
#define FF 128
#define PP 256
#define T_TOTAL 2048
#define T_TILE 128   // ticks per block (== blockDim.x)
#define P_TILE 32    // pe channels per block

__global__ __launch_bounds__(T_TILE)
void flash_reco_kernel(const float* __restrict__ pe,     // [B,F,P]
                       const float* __restrict__ ftime,  // [B,F]
                       const float* __restrict__ conf,   // [B,F]
                       const float* __restrict__ sigma_ptr,
                       float* __restrict__ out)          // [B,P,T]
{
    __shared__ float s_tb[FF];
    __shared__ float s_cs[FF];
    __shared__ int   s_idx[FF];
    __shared__ int   s_wcnt[FF / 32];

    const int tid = threadIdx.x;
    const int b   = blockIdx.z;
    const int p0  = blockIdx.y * P_TILE;
    const int t0  = blockIdx.x * T_TILE;

    const float sigma     = sigma_ptr ? __ldg(sigma_ptr) : 1.0f;
    const float inv_sigma = 1.0f / sigma;
    // weights beyond 13 sigma are below fp32 representability relative to the peak
    const float W = 13.0f * sigma;

    // ---- Phase 1: per-flash center, normalization, and tile-relevance compaction ----
    {
        const int f = tid;  // blockDim == FF == 128
        float tb = fminf(fmaxf(__ldg(&ftime[b * FF + f]) * (float)T_TOTAL, 0.0f),
                         (float)(T_TOTAL - 1));
        int lo = max(0, (int)ceilf(tb - W));
        int hi = min(T_TOTAL - 1, (int)floorf(tb + W));
        float s = 0.0f;
        for (int t = lo; t <= hi; ++t) {
            float z = ((float)t - tb) * inv_sigma;
            s += __expf(-0.5f * z * z);
        }
        s_tb[f] = tb;
        s_cs[f] = __ldg(&conf[b * FF + f]) / (s + 1e-10f);

        // does flash f touch tick range [t0, t0+T_TILE) within the 13-sigma window?
        bool rel = (tb >= (float)t0 - W) && (tb <= (float)(t0 + T_TILE - 1) + W);
        unsigned mask = __ballot_sync(0xffffffffu, rel);
        int warp = f >> 5, lane = f & 31;
        if (lane == 0) s_wcnt[warp] = __popc(mask);
        __syncthreads();
        int off = 0;
        #pragma unroll
        for (int wp = 0; wp < FF / 32; ++wp)
            if (wp < warp) off += s_wcnt[wp];
        if (rel) {
            int pos = off + __popc(mask & ((1u << lane) - 1u));
            s_idx[pos] = f;   // f-ordered -> deterministic accumulation order
        }
    }
    __syncthreads();
    const int nrel = s_wcnt[0] + s_wcnt[1] + s_wcnt[2] + s_wcnt[3];

    // ---- Phase 2: banded accumulation ----
    const float t_f = (float)(t0 + tid);
    float acc[P_TILE];
    #pragma unroll
    for (int j = 0; j < P_TILE; ++j) acc[j] = 0.0f;

    for (int k = 0; k < nrel; ++k) {
        const int f = s_idx[k];
        float z = (t_f - s_tb[f]) * inv_sigma;
        float w = s_cs[f] * __expf(-0.5f * z * z);  // underflows cleanly to 0 far away
        const float4* pef =
            reinterpret_cast<const float4*>(pe + (b * FF + f) * PP + p0);
        #pragma unroll
        for (int q = 0; q < P_TILE / 4; ++q) {
            float4 v = __ldg(&pef[q]);  // broadcast across lanes, L1-resident
            acc[q * 4 + 0] = fmaf(w, v.x, acc[q * 4 + 0]);
            acc[q * 4 + 1] = fmaf(w, v.y, acc[q * 4 + 1]);
            acc[q * 4 + 2] = fmaf(w, v.z, acc[q * 4 + 2]);
            acc[q * 4 + 3] = fmaf(w, v.w, acc[q * 4 + 3]);
        }
    }

    // ---- Phase 3: coalesced stores (threads span contiguous t) ----
    float* op = out + (size_t)(b * PP + p0) * T_TOTAL + t0 + tid;
    #pragma unroll
    for (int j = 0; j < P_TILE; ++j)
        op[(size_t)j * T_TOTAL] = acc[j];
}

extern "C" void kernel_launch(void* const* d_in, const int* in_sizes, int n_in,
                              void* d_out, int out_size)
{
    const float* pe = (const float*)d_in[0];   // flashes_pe      [B,F,P]
    const float* tm = (const float*)d_in[1];   // flashes_time    [B,F,1]
    const float* cf = (const float*)d_in[2];   // flashes_confidence [B,F,1]
    // num_ticks (int scalar, hardcoded 2048) sits before sigma when present;
    // sigma is always the LAST input in setup_inputs order.
    const float* sg = (n_in >= 4) ? (const float*)d_in[n_in - 1] : nullptr;

    dim3 grid(T_TOTAL / T_TILE, PP / P_TILE, BB);
    flash_reco_kernel<<<grid, T_TILE>>>(pe, tm, cf, sg, (float*)d_out);
}